// round 11
// baseline (speedup 1.0000x reference)
#include <cuda_runtime.h>
#include <cuda_bf16.h>
#include <cstdint>

#define DD 2048
#define BB 256
#define TT 64
#define CHW 512                      // columns per chunk
#define NCH 4

// scratch (static device arrays — no allocations)
__device__ float          g_u    [BB * DD];      // 2 MB
__device__ __nv_bfloat16  g_Eh   [BB * DD];      // 1 MB
__device__ __nv_bfloat16  g_Wh   [DD * DD];      // 8 MB: bf16(W - I)
__device__ float          g_part [NCH * BB * TT];// negative partials
__device__ float          g_ppart[NCH * BB];     // positive partials
__device__ float          g_vb   [BB];           // vb_b

// ---------------------------------------------------------------------------
// convE: E -> bf16 (256 CTAs x 256 thr, one 8-float pair per thread)
// ---------------------------------------------------------------------------
__global__ __launch_bounds__(256) void convE_kernel(const float* __restrict__ E)
{
    const int k = blockIdx.x * 256 + threadIdx.x;   // 65536 jobs
    float4 a = reinterpret_cast<const float4*>(E)[k * 2];
    float4 b = reinterpret_cast<const float4*>(E)[k * 2 + 1];
    __nv_bfloat162 p0 = __floats2bfloat162_rn(a.x, a.y);
    __nv_bfloat162 p1 = __floats2bfloat162_rn(a.z, a.w);
    __nv_bfloat162 p2 = __floats2bfloat162_rn(b.x, b.y);
    __nv_bfloat162 p3 = __floats2bfloat162_rn(b.z, b.w);
    uint4 o;
    o.x = *reinterpret_cast<uint32_t*>(&p0);
    o.y = *reinterpret_cast<uint32_t*>(&p1);
    o.z = *reinterpret_cast<uint32_t*>(&p2);
    o.w = *reinterpret_cast<uint32_t*>(&p3);
    reinterpret_cast<uint4*>(g_Eh)[k] = o;
}

// ---------------------------------------------------------------------------
// vb_kernel: g_vb[b] = dot(E[b], vb)
// ---------------------------------------------------------------------------
__global__ __launch_bounds__(256) void vb_kernel(
    const float* __restrict__ E, const float* __restrict__ vb)
{
    const int b = blockIdx.x, tid = threadIdx.x;
    const int lane = tid & 31, wid = tid >> 5;
    __shared__ float red[8];
    float pv = 0.f;
    #pragma unroll
    for (int h = 0; h < 2; h++) {
        const int i = h * 1024 + tid * 4;
        float4 e4 = *reinterpret_cast<const float4*>(&E[(size_t)b * DD + i]);
        float4 v4 = *reinterpret_cast<const float4*>(&vb[i]);
        pv += e4.x * v4.x + e4.y * v4.y + e4.z * v4.z + e4.w * v4.w;
    }
    #pragma unroll
    for (int o = 16; o > 0; o >>= 1) pv += __shfl_xor_sync(0xFFFFFFFFu, pv, o);
    if (lane == 0) red[wid] = pv;
    __syncthreads();
    if (tid == 0) {
        float v = 0.f;
        #pragma unroll
        for (int w = 0; w < 8; w++) v += red[w];
        g_vb[b] = v;
    }
}

// ---------------------------------------------------------------------------
// convW chunk: cols [cidx*512, +512) of (W - I) -> bf16.  512 CTAs x 256.
// ---------------------------------------------------------------------------
__global__ __launch_bounds__(256) void convW_kernel(
    const float* __restrict__ W, int cidx)
{
    const int j    = blockIdx.x * 256 + threadIdx.x;  // 131072 jobs
    const int row  = j >> 6;
    const int col0 = (cidx << 9) + (j & 63) * 8;
    const size_t off = (size_t)row * DD + col0;
    float4 a = *reinterpret_cast<const float4*>(&W[off]);
    float4 b = *reinterpret_cast<const float4*>(&W[off + 4]);
    const int d = row - col0;
    if (d >= 0 && d < 4)      reinterpret_cast<float*>(&a)[d]     -= 1.0f;
    else if (d >= 4 && d < 8) reinterpret_cast<float*>(&b)[d - 4] -= 1.0f;
    __nv_bfloat162 p0 = __floats2bfloat162_rn(a.x, a.y);
    __nv_bfloat162 p1 = __floats2bfloat162_rn(a.z, a.w);
    __nv_bfloat162 p2 = __floats2bfloat162_rn(b.x, b.y);
    __nv_bfloat162 p3 = __floats2bfloat162_rn(b.z, b.w);
    uint4 o;
    o.x = *reinterpret_cast<uint32_t*>(&p0);
    o.y = *reinterpret_cast<uint32_t*>(&p1);
    o.z = *reinterpret_cast<uint32_t*>(&p2);
    o.w = *reinterpret_cast<uint32_t*>(&p3);
    reinterpret_cast<uint4*>(g_Wh)[off >> 3] = o;
}

// ---------------------------------------------------------------------------
// helpers (proven)
// ---------------------------------------------------------------------------
__device__ __forceinline__ void mma16816(float* d, const uint32_t* a,
                                         uint32_t b0, uint32_t b1)
{
    asm volatile(
        "mma.sync.aligned.m16n8k16.row.col.f32.bf16.bf16.f32 "
        "{%0,%1,%2,%3}, {%4,%5,%6,%7}, {%8,%9}, {%0,%1,%2,%3};\n"
        : "+f"(d[0]), "+f"(d[1]), "+f"(d[2]), "+f"(d[3])
        : "r"(a[0]), "r"(a[1]), "r"(a[2]), "r"(a[3]), "r"(b0), "r"(b1));
}
__device__ __forceinline__ void ldsm_x4(uint32_t* r, uint32_t addr)
{
    asm volatile("ldmatrix.sync.aligned.m8n8.x4.shared.b16 {%0,%1,%2,%3}, [%4];\n"
                 : "=r"(r[0]), "=r"(r[1]), "=r"(r[2]), "=r"(r[3]) : "r"(addr));
}
__device__ __forceinline__ void ldsm_x4_t(uint32_t* r, uint32_t addr)
{
    asm volatile("ldmatrix.sync.aligned.m8n8.x4.trans.shared.b16 {%0,%1,%2,%3}, [%4];\n"
                 : "=r"(r[0]), "=r"(r[1]), "=r"(r[2]), "=r"(r[3]) : "r"(addr));
}
__device__ __forceinline__ void cp16(uint32_t saddr, const void* gaddr)
{
    asm volatile("cp.async.cg.shared.global [%0], [%1], 16;\n"
                 :: "r"(saddr), "l"(gaddr) : "memory");
}

// ---------------------------------------------------------------------------
// GEMM chunk (round-10 proven 6-stage ring; bn offset by bn0). Grid (8,4).
// ---------------------------------------------------------------------------
__global__ __launch_bounds__(256) void gemm_u_kernel(
    const float* __restrict__ E, const float* __restrict__ hb, int bn0)
{
    extern __shared__ __align__(1024) char smem[];
    const uint32_t base = (uint32_t)__cvta_generic_to_shared(smem);

    const int tid  = threadIdx.x;
    const int lane = tid & 31;
    const int wid  = tid >> 5;
    const int wm   = (wid >> 2) << 5;
    const int wn   = (wid & 3) << 4;
    const int bm   = blockIdx.y << 6;
    const int bn   = bn0 + (blockIdx.x << 6);

    float acc[2][2][4];
    #pragma unroll
    for (int i = 0; i < 2; i++)
        #pragma unroll
        for (int j = 0; j < 2; j++)
            #pragma unroll
            for (int k = 0; k < 4; k++) acc[i][j][k] = 0.f;

    const int r0 = tid >> 3;
    const int c0 = tid & 7;
    const uint32_t swzOff  = (uint32_t)((r0 << 7) + ((c0 ^ (r0 & 7)) << 4));
    const uint32_t swzOff2 = swzOff + (32 << 7);

    const __nv_bfloat16* gA  = g_Eh + (size_t)(bm + r0) * DD + c0 * 8;
    const __nv_bfloat16* gA2 = gA + (size_t)32 * DD;
    const __nv_bfloat16* gB  = g_Wh + (size_t)r0 * DD + bn + c0 * 8;
    const __nv_bfloat16* gB2 = gB + (size_t)32 * DD;

    const int l15 = lane & 15;
    const int l7  = lane & 7;
    const int kcB = lane >> 4;
    uint32_t aRow[2];
    #pragma unroll
    for (int im = 0; im < 2; im++) aRow[im] = (uint32_t)((wm + im * 16 + l15) << 7);
    const int nChunkBase = wn >> 3;

    #define LOAD_TILES(stg, k0)                                            \
        {                                                                  \
            const uint32_t sa = base + (uint32_t)((stg) * 8192);           \
            const uint32_t sb = base + 49152u + (uint32_t)((stg) * 8192);  \
            cp16(sa + swzOff,  gA  + (k0));                                \
            cp16(sa + swzOff2, gA2 + (k0));                                \
            cp16(sb + swzOff,  gB  + (size_t)(k0) * DD);                   \
            cp16(sb + swzOff2, gB2 + (size_t)(k0) * DD);                   \
            asm volatile("cp.async.commit_group;\n" ::: "memory");         \
        }

    #pragma unroll
    for (int p = 0; p < 5; p++) LOAD_TILES(p, p * 64);

    const int NIT = DD / 64;   // 32
    for (int it = 0; it < NIT; it++) {
        if (it + 4 < NIT)
            asm volatile("cp.async.wait_group 4;\n" ::: "memory");
        else
            asm volatile("cp.async.wait_group 0;\n" ::: "memory");
        __syncthreads();

        if (it + 5 < NIT) LOAD_TILES((it + 5) % 6, (it + 5) * 64);

        const int s = it % 6;
        const uint32_t sa = base + (uint32_t)(s * 8192);
        const uint32_t sb = base + 49152u + (uint32_t)(s * 8192);
        #pragma unroll
        for (int kk = 0; kk < 4; kk++) {
            uint32_t a[2][4], b[4];
            const int kchunk = kk * 2 + kcB;
            #pragma unroll
            for (int im = 0; im < 2; im++)
                ldsm_x4(a[im], sa + aRow[im] + (uint32_t)((kchunk ^ l7) << 4));
            {
                const int krow = kk * 16 + l15;
                const int nchunk = nChunkBase + kcB;
                ldsm_x4_t(b, sb + (uint32_t)(krow << 7)
                               + (uint32_t)((nchunk ^ (krow & 7)) << 4));
            }
            #pragma unroll
            for (int im = 0; im < 2; im++) {
                mma16816(acc[im][0], a[im], b[0], b[1]);
                mma16816(acc[im][1], a[im], b[2], b[3]);
            }
        }
    }
    #undef LOAD_TILES

    #pragma unroll
    for (int im = 0; im < 2; im++) {
        const int row0e = bm + wm + im * 16 + (lane >> 2);
        #pragma unroll
        for (int in = 0; in < 2; in++) {
            const int col = bn + wn + in * 8 + ((lane & 3) << 1);
            const float h0 = hb[col], h1 = hb[col + 1];
            g_u[(size_t)row0e * DD + col]
                = acc[im][in][0] + E[(size_t)row0e * DD + col] + h0;
            g_u[(size_t)row0e * DD + col + 1]
                = acc[im][in][1] + E[(size_t)row0e * DD + col + 1] + h1;
            g_u[(size_t)(row0e + 8) * DD + col]
                = acc[im][in][2] + E[(size_t)(row0e + 8) * DD + col] + h0;
            g_u[(size_t)(row0e + 8) * DD + col + 1]
                = acc[im][in][3] + E[(size_t)(row0e + 8) * DD + col + 1] + h1;
        }
    }
}

// ---------------------------------------------------------------------------
// score chunk: partial dots over 512 cols. grid (256,8) x 128 thr.
// CTA (b,tc): 8 t-rows; warp w -> rows tc*8+2w,+1.
// ---------------------------------------------------------------------------
__global__ __launch_bounds__(128, 16) void score_kernel(
    const float* __restrict__ theo, const float* __restrict__ cand, int cidx)
{
    const int b    = blockIdx.x;
    const int tc   = blockIdx.y;
    const int tid  = threadIdx.x;
    const int lane = tid & 31;
    const int wid  = tid >> 5;
    const int c0   = cidx << 9;

    __shared__ float u_s[CHW];
    __shared__ float redp[4];

    float pp = 0.f;
    {
        const int i = tid * 4;   // 128*4 = 512 exactly
        float4 u4 = *reinterpret_cast<const float4*>(&g_u[(size_t)b * DD + c0 + i]);
        *reinterpret_cast<float4*>(&u_s[i]) = u4;
        if (tc == 0) {
            float4 c4 = *reinterpret_cast<const float4*>(&cand[(size_t)b * DD + c0 + i]);
            pp = u4.x * c4.x + u4.y * c4.y + u4.z * c4.z + u4.w * c4.w;
        }
    }
    if (tc == 0) {
        #pragma unroll
        for (int o = 16; o > 0; o >>= 1) pp += __shfl_xor_sync(0xFFFFFFFFu, pp, o);
        if (lane == 0) redp[wid] = pp;
    }
    __syncthreads();
    if (tc == 0 && tid == 0)
        g_ppart[cidx * BB + b] = redp[0] + redp[1] + redp[2] + redp[3];

    const int t0 = tc * 8 + wid * 2;
    const float* ra = theo + ((size_t)b * TT + t0) * DD + c0;
    const float* rb = ra + DD;

    float s0 = 0.f, s1 = 0.f;
    #pragma unroll
    for (int it2 = 0; it2 < 4; it2++) {
        const int idx = it2 * 128 + lane * 4;
        float4 x = __ldcs(reinterpret_cast<const float4*>(&ra[idx]));
        float4 y = __ldcs(reinterpret_cast<const float4*>(&rb[idx]));
        float4 u = *reinterpret_cast<const float4*>(&u_s[idx]);
        s0 += x.x * u.x + x.y * u.y + x.z * u.z + x.w * u.w;
        s1 += y.x * u.x + y.y * u.y + y.z * u.z + y.w * u.w;
    }
    #pragma unroll
    for (int o = 16; o > 0; o >>= 1) {
        s0 += __shfl_xor_sync(0xFFFFFFFFu, s0, o);
        s1 += __shfl_xor_sync(0xFFFFFFFFu, s1, o);
    }
    if (lane == 0) {
        g_part[(cidx * BB + b) * TT + t0]     = s0;
        g_part[(cidx * BB + b) * TT + t0 + 1] = s1;
    }
}

// ---------------------------------------------------------------------------
// final: out[b,0] = sum ppart + vb ; out[b,1+t] = sum part + vb
// ---------------------------------------------------------------------------
__global__ __launch_bounds__(128) void final_kernel(float* __restrict__ out)
{
    const int b = blockIdx.x, t = threadIdx.x;
    const float vbb = g_vb[b];
    if (t < TT) {
        float s = g_part[(0 * BB + b) * TT + t] + g_part[(1 * BB + b) * TT + t]
                + g_part[(2 * BB + b) * TT + t] + g_part[(3 * BB + b) * TT + t];
        out[b * (TT + 1) + 1 + t] = s + vbb;
    } else if (t == TT) {
        float p = g_ppart[0 * BB + b] + g_ppart[1 * BB + b]
                + g_ppart[2 * BB + b] + g_ppart[3 * BB + b];
        out[b * (TT + 1)] = p + vbb;
    }
}

// ---------------------------------------------------------------------------
// launch: dual-stream fork/join (capturable). Chunks 1-3 conv+gemm on side
// stream hidden under the BW-bound score chain.
// ---------------------------------------------------------------------------
extern "C" void kernel_launch(void* const* d_in, const int* in_sizes, int n_in,
                              void* d_out, int out_size)
{
    const float* E    = (const float*)d_in[0];
    const float* theo = (const float*)d_in[1];
    const float* cand = (const float*)d_in[2];
    const float* W    = (const float*)d_in[3];
    const float* vb   = (const float*)d_in[4];
    const float* hb   = (const float*)d_in[5];
    float*       out  = (float*)d_out;

    static cudaStream_t s1 = nullptr;
    static cudaEvent_t evE, evG2, evS3;
    if (!s1) {
        cudaStreamCreateWithFlags(&s1, cudaStreamNonBlocking);
        cudaEventCreateWithFlags(&evE,  cudaEventDisableTiming);
        cudaEventCreateWithFlags(&evG2, cudaEventDisableTiming);
        cudaEventCreateWithFlags(&evS3, cudaEventDisableTiming);
        const int SMEM_ = 12 * 8192;
        cudaFuncSetAttribute(gemm_u_kernel,
                             cudaFuncAttributeMaxDynamicSharedMemorySize, SMEM_);
    }
    const int SMEM = 12 * 8192;   // 96 KB

    // stream 0: E convert, then chunk-0 path
    convE_kernel<<<256, 256>>>(E);
    cudaEventRecord(evE, 0);
    cudaStreamWaitEvent(s1, evE, 0);

    // side stream: vb + chunks 1..3 conv+gemm, then scores 1,3
    vb_kernel<<<BB, 256, 0, s1>>>(E, vb);
    convW_kernel<<<512, 256, 0, s1>>>(W, 1);
    gemm_u_kernel<<<dim3(8, 4), 256, SMEM, s1>>>(E, hb, 1 * CHW);
    convW_kernel<<<512, 256, 0, s1>>>(W, 2);
    gemm_u_kernel<<<dim3(8, 4), 256, SMEM, s1>>>(E, hb, 2 * CHW);
    cudaEventRecord(evG2, s1);
    convW_kernel<<<512, 256, 0, s1>>>(W, 3);
    gemm_u_kernel<<<dim3(8, 4), 256, SMEM, s1>>>(E, hb, 3 * CHW);
    score_kernel<<<dim3(BB, 8), 128, 0, s1>>>(theo, cand, 1);
    score_kernel<<<dim3(BB, 8), 128, 0, s1>>>(theo, cand, 3);
    cudaEventRecord(evS3, s1);

    // stream 0: chunk 0 conv+gemm+score, chunk 2 score, final
    convW_kernel<<<512, 256>>>(W, 0);
    gemm_u_kernel<<<dim3(8, 4), 256, SMEM>>>(E, hb, 0);
    score_kernel<<<dim3(BB, 8), 128>>>(theo, cand, 0);
    cudaStreamWaitEvent(0, evG2, 0);
    score_kernel<<<dim3(BB, 8), 128>>>(theo, cand, 2);
    cudaStreamWaitEvent(0, evS3, 0);
    final_kernel<<<BB, 128>>>(out);
}

// round 13
// speedup vs baseline: 1.0329x; 1.0329x over previous
#include <cuda_runtime.h>
#include <cuda_bf16.h>
#include <cstdint>

#define DD 2048
#define BB 256
#define TT 64

// scratch (static device arrays — no allocations)
__device__ float          g_u [BB * DD];   // 2 MB
__device__ __nv_bfloat16  g_Eh[BB * DD];   // 1 MB
__device__ __nv_bfloat16  g_Wh[DD * DD];   // 8 MB: bf16(W - I)
__device__ int            g_cntE[32];      // per-K-chunk readiness (E cols)
__device__ int            g_cntW[32];      // per-K-chunk readiness (W rows)

// ---------------------------------------------------------------------------
// reset: zero the chunk counters (every replay)
// ---------------------------------------------------------------------------
__global__ void reset_kernel()
{
    const int t = threadIdx.x;
    if (t < 32) { g_cntE[t] = 0; g_cntW[t] = 0; }
}

__device__ __forceinline__ uint4 pack8(const float4& a, const float4& b)
{
    __nv_bfloat162 p0 = __floats2bfloat162_rn(a.x, a.y);
    __nv_bfloat162 p1 = __floats2bfloat162_rn(a.z, a.w);
    __nv_bfloat162 p2 = __floats2bfloat162_rn(b.x, b.y);
    __nv_bfloat162 p3 = __floats2bfloat162_rn(b.z, b.w);
    uint4 o;
    o.x = *reinterpret_cast<uint32_t*>(&p0);
    o.y = *reinterpret_cast<uint32_t*>(&p1);
    o.z = *reinterpret_cast<uint32_t*>(&p2);
    o.w = *reinterpret_cast<uint32_t*>(&p3);
    return o;
}

// ---------------------------------------------------------------------------
// convE: E -> bf16 by K-chunk (64 cols). grid 256: cc=blk>>3, rb=blk&7.
// ---------------------------------------------------------------------------
__global__ __launch_bounds__(256) void convE_kernel(const float* __restrict__ E)
{
    const int cc  = blockIdx.x >> 3;
    const int rb  = blockIdx.x & 7;
    const int row = rb * 32 + (threadIdx.x >> 3);
    const int col = cc * 64 + (threadIdx.x & 7) * 8;
    const size_t off = (size_t)row * DD + col;
    float4 a = *reinterpret_cast<const float4*>(&E[off]);
    float4 b = *reinterpret_cast<const float4*>(&E[off + 4]);
    reinterpret_cast<uint4*>(g_Eh)[off >> 3] = pack8(a, b);
    __syncthreads();
    if (threadIdx.x == 0) { __threadfence(); atomicAdd(&g_cntE[cc], 1); }
}

// ---------------------------------------------------------------------------
// convW: (W - I) -> bf16, one row per CTA (row = K index). grid 2048.
// ---------------------------------------------------------------------------
__global__ __launch_bounds__(256) void convW_kernel(const float* __restrict__ W)
{
    const int row  = blockIdx.x;
    const int col0 = threadIdx.x * 8;
    const size_t off = (size_t)row * DD + col0;
    float4 a = *reinterpret_cast<const float4*>(&W[off]);
    float4 b = *reinterpret_cast<const float4*>(&W[off + 4]);
    const int d = row - col0;
    if (d >= 0 && d < 4)      reinterpret_cast<float*>(&a)[d]     -= 1.0f;
    else if (d >= 4 && d < 8) reinterpret_cast<float*>(&b)[d - 4] -= 1.0f;
    reinterpret_cast<uint4*>(g_Wh)[off >> 3] = pack8(a, b);
    __syncthreads();
    if (threadIdx.x == 0) { __threadfence(); atomicAdd(&g_cntW[row >> 6], 1); }
}

// ---------------------------------------------------------------------------
// helpers (proven)
// ---------------------------------------------------------------------------
__device__ __forceinline__ void mma16816(float* d, const uint32_t* a,
                                         uint32_t b0, uint32_t b1)
{
    asm volatile(
        "mma.sync.aligned.m16n8k16.row.col.f32.bf16.bf16.f32 "
        "{%0,%1,%2,%3}, {%4,%5,%6,%7}, {%8,%9}, {%0,%1,%2,%3};\n"
        : "+f"(d[0]), "+f"(d[1]), "+f"(d[2]), "+f"(d[3])
        : "r"(a[0]), "r"(a[1]), "r"(a[2]), "r"(a[3]), "r"(b0), "r"(b1));
}
__device__ __forceinline__ void ldsm_x4(uint32_t* r, uint32_t addr)
{
    asm volatile("ldmatrix.sync.aligned.m8n8.x4.shared.b16 {%0,%1,%2,%3}, [%4];\n"
                 : "=r"(r[0]), "=r"(r[1]), "=r"(r[2]), "=r"(r[3]) : "r"(addr));
}
__device__ __forceinline__ void ldsm_x4_t(uint32_t* r, uint32_t addr)
{
    asm volatile("ldmatrix.sync.aligned.m8n8.x4.trans.shared.b16 {%0,%1,%2,%3}, [%4];\n"
                 : "=r"(r[0]), "=r"(r[1]), "=r"(r[2]), "=r"(r[3]) : "r"(addr));
}
__device__ __forceinline__ void cp16(uint32_t saddr, const void* gaddr)
{
    asm volatile("cp.async.cg.shared.global [%0], [%1], 16;\n"
                 :: "r"(saddr), "l"(gaddr) : "memory");
}

// lane-0 poll (acquire) until chunk st of both E and W is converted
__device__ __forceinline__ void wait_chunk(int st)
{
    if ((threadIdx.x & 31) == 0) {
        for (;;) {
            int e, w;
            asm volatile("ld.acquire.gpu.global.b32 %0, [%1];"
                         : "=r"(e) : "l"(g_cntE + st));
            asm volatile("ld.acquire.gpu.global.b32 %0, [%1];"
                         : "=r"(w) : "l"(g_cntW + st));
            if (e >= 8 && w >= 64) break;
            __nanosleep(64);
        }
    }
    __syncwarp();
}

// ---------------------------------------------------------------------------
// Kernel A: tensor-core GEMM  U = Eh @ Wh + E + hb  (6-stage ring, paced by
// converter counters; runs concurrently with converters on another stream)
// ---------------------------------------------------------------------------
__global__ __launch_bounds__(256) void gemm_u_kernel(
    const float* __restrict__ E, const float* __restrict__ hb)
{
    extern __shared__ __align__(1024) char smem[];
    const uint32_t base = (uint32_t)__cvta_generic_to_shared(smem);

    const int tid  = threadIdx.x;
    const int lane = tid & 31;
    const int wid  = tid >> 5;
    const int wm   = (wid >> 2) << 5;
    const int wn   = (wid & 3) << 4;
    const int bm   = blockIdx.y << 6;
    const int bn   = blockIdx.x << 6;

    float acc[2][2][4];
    #pragma unroll
    for (int i = 0; i < 2; i++)
        #pragma unroll
        for (int j = 0; j < 2; j++)
            #pragma unroll
            for (int k = 0; k < 4; k++) acc[i][j][k] = 0.f;

    const int r0 = tid >> 3;
    const int c0 = tid & 7;
    const uint32_t swzOff  = (uint32_t)((r0 << 7) + ((c0 ^ (r0 & 7)) << 4));
    const uint32_t swzOff2 = swzOff + (32 << 7);

    const __nv_bfloat16* gA  = g_Eh + (size_t)(bm + r0) * DD + c0 * 8;
    const __nv_bfloat16* gA2 = gA + (size_t)32 * DD;
    const __nv_bfloat16* gB  = g_Wh + (size_t)r0 * DD + bn + c0 * 8;
    const __nv_bfloat16* gB2 = gB + (size_t)32 * DD;

    const int l15 = lane & 15;
    const int l7  = lane & 7;
    const int kcB = lane >> 4;
    uint32_t aRow[2];
    #pragma unroll
    for (int im = 0; im < 2; im++) aRow[im] = (uint32_t)((wm + im * 16 + l15) << 7);
    const int nChunkBase = wn >> 3;

    #define LOAD_TILES(stg, k0)                                            \
        {                                                                  \
            const uint32_t sa = base + (uint32_t)((stg) * 8192);           \
            const uint32_t sb = base + 49152u + (uint32_t)((stg) * 8192);  \
            cp16(sa + swzOff,  gA  + (k0));                                \
            cp16(sa + swzOff2, gA2 + (k0));                                \
            cp16(sb + swzOff,  gB  + (size_t)(k0) * DD);                   \
            cp16(sb + swzOff2, gB2 + (size_t)(k0) * DD);                   \
            asm volatile("cp.async.commit_group;\n" ::: "memory");         \
        }

    #pragma unroll
    for (int p = 0; p < 5; p++) { wait_chunk(p); LOAD_TILES(p, p * 64); }

    const int NIT = DD / 64;   // 32
    for (int it = 0; it < NIT; it++) {
        if (it + 4 < NIT)
            asm volatile("cp.async.wait_group 4;\n" ::: "memory");
        else
            asm volatile("cp.async.wait_group 0;\n" ::: "memory");
        __syncthreads();

        if (it + 5 < NIT) { wait_chunk(it + 5); LOAD_TILES((it + 5) % 6, (it + 5) * 64); }

        const int s = it % 6;
        const uint32_t sa = base + (uint32_t)(s * 8192);
        const uint32_t sb = base + 49152u + (uint32_t)(s * 8192);
        #pragma unroll
        for (int kk = 0; kk < 4; kk++) {
            uint32_t a[2][4], b[4];
            const int kchunk = kk * 2 + kcB;
            #pragma unroll
            for (int im = 0; im < 2; im++)
                ldsm_x4(a[im], sa + aRow[im] + (uint32_t)((kchunk ^ l7) << 4));
            {
                const int krow = kk * 16 + l15;
                const int nchunk = nChunkBase + kcB;
                ldsm_x4_t(b, sb + (uint32_t)(krow << 7)
                               + (uint32_t)((nchunk ^ (krow & 7)) << 4));
            }
            #pragma unroll
            for (int im = 0; im < 2; im++) {
                mma16816(acc[im][0], a[im], b[0], b[1]);
                mma16816(acc[im][1], a[im], b[2], b[3]);
            }
        }
    }
    #undef LOAD_TILES

    // epilogue: u = acc + E (exact identity) + hb
    #pragma unroll
    for (int im = 0; im < 2; im++) {
        const int row0e = bm + wm + im * 16 + (lane >> 2);
        #pragma unroll
        for (int in = 0; in < 2; in++) {
            const int col = bn + wn + in * 8 + ((lane & 3) << 1);
            const float h0 = hb[col], h1 = hb[col + 1];
            g_u[(size_t)row0e * DD + col]
                = acc[im][in][0] + E[(size_t)row0e * DD + col] + h0;
            g_u[(size_t)row0e * DD + col + 1]
                = acc[im][in][1] + E[(size_t)row0e * DD + col + 1] + h1;
            g_u[(size_t)(row0e + 8) * DD + col]
                = acc[im][in][2] + E[(size_t)(row0e + 8) * DD + col] + h0;
            g_u[(size_t)(row0e + 8) * DD + col + 1]
                = acc[im][in][3] + E[(size_t)(row0e + 8) * DD + col + 1] + h1;
        }
    }
}

// ---------------------------------------------------------------------------
// Kernel B: scoring (round-8/10 passing version, verbatim). Single wave:
// grid (256, 8) x 128 thr, 16 CTAs/SM.
// ---------------------------------------------------------------------------
__global__ __launch_bounds__(128, 16) void score_kernel(
    const float* __restrict__ E,
    const float* __restrict__ theo,
    const float* __restrict__ cand,
    const float* __restrict__ vb,
    float* __restrict__ out)
{
    const int b    = blockIdx.x;
    const int tc   = blockIdx.y;       // 0..7
    const int tid  = threadIdx.x;
    const int lane = tid & 31;
    const int wid  = tid >> 5;         // 0..3

    __shared__ float u_s[DD];
    __shared__ float red[8];
    __shared__ float s_vb, s_pos;

    float pv = 0.f, pp = 0.f;
    #pragma unroll
    for (int h = 0; h < 4; h++) {
        const int i = h * 512 + tid * 4;
        float4 u4 = *reinterpret_cast<const float4*>(&g_u[(size_t)b * DD + i]);
        *reinterpret_cast<float4*>(&u_s[i]) = u4;
        float4 e4 = *reinterpret_cast<const float4*>(&E[(size_t)b * DD + i]);
        float4 v4 = *reinterpret_cast<const float4*>(&vb[i]);
        pv += e4.x * v4.x + e4.y * v4.y + e4.z * v4.z + e4.w * v4.w;
        if (tc == 0) {
            float4 c4 = *reinterpret_cast<const float4*>(&cand[(size_t)b * DD + i]);
            pp += u4.x * c4.x + u4.y * c4.y + u4.z * c4.z + u4.w * c4.w;
        }
    }
    #pragma unroll
    for (int o = 16; o > 0; o >>= 1) {
        pv += __shfl_xor_sync(0xFFFFFFFFu, pv, o);
        pp += __shfl_xor_sync(0xFFFFFFFFu, pp, o);
    }
    if (lane == 0) { red[wid] = pv; red[4 + wid] = pp; }
    __syncthreads();
    if (tid == 0) {
        float v = red[0] + red[1] + red[2] + red[3];
        float p = red[4] + red[5] + red[6] + red[7];
        s_vb  = v;
        s_pos = p + v;
    }
    __syncthreads();
    const float vbb = s_vb;

    const int t0 = tc * 8 + wid * 2;
    const float4* ra  = reinterpret_cast<const float4*>(&theo[((size_t)b * TT + t0) * DD]);
    const float4* rb  = ra + DD / 4;
    const float4* u4p = reinterpret_cast<const float4*>(u_s);

    float s0 = 0.f, s1 = 0.f;
    #pragma unroll 4
    for (int i = lane; i < DD / 4; i += 32) {
        float4 x = __ldcs(&ra[i]);
        float4 y = __ldcs(&rb[i]);
        float4 u = u4p[i];
        s0 += x.x * u.x + x.y * u.y + x.z * u.z + x.w * u.w;
        s1 += y.x * u.x + y.y * u.y + y.z * u.z + y.w * u.w;
    }
    #pragma unroll
    for (int o = 16; o > 0; o >>= 1) {
        s0 += __shfl_xor_sync(0xFFFFFFFFu, s0, o);
        s1 += __shfl_xor_sync(0xFFFFFFFFu, s1, o);
    }
    if (lane == 0) {
        out[b * (TT + 1) + 1 + t0]     = s0 + vbb;
        out[b * (TT + 1) + 1 + t0 + 1] = s1 + vbb;
    }
    if (tc == 0 && tid == 0) out[b * (TT + 1)] = s_pos;
}

// ---------------------------------------------------------------------------
// launch: reset -> fork {converters on s2 ∥ paced GEMM on s1} -> join BOTH
// streams back into stream 0 -> score.  (All forks rejoin: capturable.)
// ---------------------------------------------------------------------------
extern "C" void kernel_launch(void* const* d_in, const int* in_sizes, int n_in,
                              void* d_out, int out_size)
{
    const float* E    = (const float*)d_in[0];
    const float* theo = (const float*)d_in[1];
    const float* cand = (const float*)d_in[2];
    const float* W    = (const float*)d_in[3];
    const float* vb   = (const float*)d_in[4];
    const float* hb   = (const float*)d_in[5];
    float*       out  = (float*)d_out;

    static cudaStream_t s1 = nullptr, s2 = nullptr;
    static cudaEvent_t evR, evG, evC;
    if (!s1) {
        cudaStreamCreateWithFlags(&s1, cudaStreamNonBlocking);
        cudaStreamCreateWithFlags(&s2, cudaStreamNonBlocking);
        cudaEventCreateWithFlags(&evR, cudaEventDisableTiming);
        cudaEventCreateWithFlags(&evG, cudaEventDisableTiming);
        cudaEventCreateWithFlags(&evC, cudaEventDisableTiming);
        cudaFuncSetAttribute(gemm_u_kernel,
                             cudaFuncAttributeMaxDynamicSharedMemorySize, 12 * 8192);
    }
    const int SMEM = 12 * 8192;   // 96 KB

    reset_kernel<<<1, 32>>>();
    cudaEventRecord(evR, 0);
    cudaStreamWaitEvent(s1, evR, 0);
    cudaStreamWaitEvent(s2, evR, 0);

    // converter stream: E chunks first (fast), then W rows in K order
    convE_kernel<<<256, 256, 0, s2>>>(E);
    convW_kernel<<<2048, 256, 0, s2>>>(W);
    cudaEventRecord(evC, s2);

    // consumer stream: full-grid GEMM paced by chunk counters
    gemm_u_kernel<<<dim3(DD / 64, BB / 64), 256, SMEM, s1>>>(E, hb);
    cudaEventRecord(evG, s1);

    // join BOTH forks back into the origin stream, then score
    cudaStreamWaitEvent(0, evG, 0);
    cudaStreamWaitEvent(0, evC, 0);
    score_kernel<<<dim3(BB, 8), 128>>>(E, theo, cand, vb, out);
}

// round 14
// speedup vs baseline: 1.5149x; 1.4666x over previous
#include <cuda_runtime.h>
#include <cuda_bf16.h>
#include <cstdint>

#define DD 2048
#define BB 256
#define TT 64

// scratch (static device arrays — no allocations)
__device__ float          g_u [BB * DD];   // 2 MB
__device__ __nv_bfloat16  g_Eh[BB * DD];   // 1 MB
__device__ __nv_bfloat16  g_Wh[DD * DD];   // 8 MB: bf16(W - I)

// ---------------------------------------------------------------------------
// Kernel 0: convert (R10 proven). 1 thread = 2 float4 -> one uint4 store.
// ---------------------------------------------------------------------------
__global__ __launch_bounds__(256) void convert_kernel(
    const float* __restrict__ E, const float* __restrict__ W)
{
    const int NWP = DD * DD / 8;              // 524288 W pairs
    const int j = blockIdx.x * 256 + threadIdx.x;
    if (j < NWP) {
        float4 a = reinterpret_cast<const float4*>(W)[j * 2];
        float4 b = reinterpret_cast<const float4*>(W)[j * 2 + 1];
        const int fbase = j * 8;
        const int r = fbase >> 11;
        const int d = r - (fbase & (DD - 1));
        if (d >= 0 && d < 4)      reinterpret_cast<float*>(&a)[d]     -= 1.0f;
        else if (d >= 4 && d < 8) reinterpret_cast<float*>(&b)[d - 4] -= 1.0f;
        __nv_bfloat162 p0 = __floats2bfloat162_rn(a.x, a.y);
        __nv_bfloat162 p1 = __floats2bfloat162_rn(a.z, a.w);
        __nv_bfloat162 p2 = __floats2bfloat162_rn(b.x, b.y);
        __nv_bfloat162 p3 = __floats2bfloat162_rn(b.z, b.w);
        uint4 o;
        o.x = *reinterpret_cast<uint32_t*>(&p0);
        o.y = *reinterpret_cast<uint32_t*>(&p1);
        o.z = *reinterpret_cast<uint32_t*>(&p2);
        o.w = *reinterpret_cast<uint32_t*>(&p3);
        reinterpret_cast<uint4*>(g_Wh)[j] = o;
    } else {
        const int k = j - NWP;
        float4 a = reinterpret_cast<const float4*>(E)[k * 2];
        float4 b = reinterpret_cast<const float4*>(E)[k * 2 + 1];
        __nv_bfloat162 p0 = __floats2bfloat162_rn(a.x, a.y);
        __nv_bfloat162 p1 = __floats2bfloat162_rn(a.z, a.w);
        __nv_bfloat162 p2 = __floats2bfloat162_rn(b.x, b.y);
        __nv_bfloat162 p3 = __floats2bfloat162_rn(b.z, b.w);
        uint4 o;
        o.x = *reinterpret_cast<uint32_t*>(&p0);
        o.y = *reinterpret_cast<uint32_t*>(&p1);
        o.z = *reinterpret_cast<uint32_t*>(&p2);
        o.w = *reinterpret_cast<uint32_t*>(&p3);
        reinterpret_cast<uint4*>(g_Eh)[k] = o;
    }
}

// ---------------------------------------------------------------------------
// helpers (proven)
// ---------------------------------------------------------------------------
__device__ __forceinline__ void mma16816(float* d, const uint32_t* a,
                                         uint32_t b0, uint32_t b1)
{
    asm volatile(
        "mma.sync.aligned.m16n8k16.row.col.f32.bf16.bf16.f32 "
        "{%0,%1,%2,%3}, {%4,%5,%6,%7}, {%8,%9}, {%0,%1,%2,%3};\n"
        : "+f"(d[0]), "+f"(d[1]), "+f"(d[2]), "+f"(d[3])
        : "r"(a[0]), "r"(a[1]), "r"(a[2]), "r"(a[3]), "r"(b0), "r"(b1));
}
__device__ __forceinline__ void ldsm_x4(uint32_t* r, uint32_t addr)
{
    asm volatile("ldmatrix.sync.aligned.m8n8.x4.shared.b16 {%0,%1,%2,%3}, [%4];\n"
                 : "=r"(r[0]), "=r"(r[1]), "=r"(r[2]), "=r"(r[3]) : "r"(addr));
}
__device__ __forceinline__ void ldsm_x4_t(uint32_t* r, uint32_t addr)
{
    asm volatile("ldmatrix.sync.aligned.m8n8.x4.trans.shared.b16 {%0,%1,%2,%3}, [%4];\n"
                 : "=r"(r[0]), "=r"(r[1]), "=r"(r[2]), "=r"(r[3]) : "r"(addr));
}
__device__ __forceinline__ void cp16(uint32_t saddr, const void* gaddr)
{
    asm volatile("cp.async.cg.shared.global [%0], [%1], 16;\n"
                 :: "r"(saddr), "l"(gaddr) : "memory");
}

// ---------------------------------------------------------------------------
// Kernel A: tensor-core GEMM  U = Eh @ Wh + E + hb  (R10 proven 6-stage ring)
// ---------------------------------------------------------------------------
__global__ __launch_bounds__(256) void gemm_u_kernel(
    const float* __restrict__ E, const float* __restrict__ hb)
{
    extern __shared__ __align__(1024) char smem[];
    const uint32_t base = (uint32_t)__cvta_generic_to_shared(smem);

    const int tid  = threadIdx.x;
    const int lane = tid & 31;
    const int wid  = tid >> 5;
    const int wm   = (wid >> 2) << 5;
    const int wn   = (wid & 3) << 4;
    const int bm   = blockIdx.y << 6;
    const int bn   = blockIdx.x << 6;

    float acc[2][2][4];
    #pragma unroll
    for (int i = 0; i < 2; i++)
        #pragma unroll
        for (int j = 0; j < 2; j++)
            #pragma unroll
            for (int k = 0; k < 4; k++) acc[i][j][k] = 0.f;

    const int r0 = tid >> 3;
    const int c0 = tid & 7;
    const uint32_t swzOff  = (uint32_t)((r0 << 7) + ((c0 ^ (r0 & 7)) << 4));
    const uint32_t swzOff2 = swzOff + (32 << 7);

    const __nv_bfloat16* gA  = g_Eh + (size_t)(bm + r0) * DD + c0 * 8;
    const __nv_bfloat16* gA2 = gA + (size_t)32 * DD;
    const __nv_bfloat16* gB  = g_Wh + (size_t)r0 * DD + bn + c0 * 8;
    const __nv_bfloat16* gB2 = gB + (size_t)32 * DD;

    const int l15 = lane & 15;
    const int l7  = lane & 7;
    const int kcB = lane >> 4;
    uint32_t aRow[2];
    #pragma unroll
    for (int im = 0; im < 2; im++) aRow[im] = (uint32_t)((wm + im * 16 + l15) << 7);
    const int nChunkBase = wn >> 3;

    #define LOAD_TILES(stg, k0)                                            \
        {                                                                  \
            const uint32_t sa = base + (uint32_t)((stg) * 8192);           \
            const uint32_t sb = base + 49152u + (uint32_t)((stg) * 8192);  \
            cp16(sa + swzOff,  gA  + (k0));                                \
            cp16(sa + swzOff2, gA2 + (k0));                                \
            cp16(sb + swzOff,  gB  + (size_t)(k0) * DD);                   \
            cp16(sb + swzOff2, gB2 + (size_t)(k0) * DD);                   \
            asm volatile("cp.async.commit_group;\n" ::: "memory");         \
        }

    #pragma unroll
    for (int p = 0; p < 5; p++) LOAD_TILES(p, p * 64);

    const int NIT = DD / 64;   // 32
    for (int it = 0; it < NIT; it++) {
        if (it + 4 < NIT)
            asm volatile("cp.async.wait_group 4;\n" ::: "memory");
        else
            asm volatile("cp.async.wait_group 0;\n" ::: "memory");
        __syncthreads();

        if (it + 5 < NIT) LOAD_TILES((it + 5) % 6, (it + 5) * 64);

        const int s = it % 6;
        const uint32_t sa = base + (uint32_t)(s * 8192);
        const uint32_t sb = base + 49152u + (uint32_t)(s * 8192);
        #pragma unroll
        for (int kk = 0; kk < 4; kk++) {
            uint32_t a[2][4], b[4];
            const int kchunk = kk * 2 + kcB;
            #pragma unroll
            for (int im = 0; im < 2; im++)
                ldsm_x4(a[im], sa + aRow[im] + (uint32_t)((kchunk ^ l7) << 4));
            {
                const int krow = kk * 16 + l15;
                const int nchunk = nChunkBase + kcB;
                ldsm_x4_t(b, sb + (uint32_t)(krow << 7)
                               + (uint32_t)((nchunk ^ (krow & 7)) << 4));
            }
            #pragma unroll
            for (int im = 0; im < 2; im++) {
                mma16816(acc[im][0], a[im], b[0], b[1]);
                mma16816(acc[im][1], a[im], b[2], b[3]);
            }
        }
    }
    #undef LOAD_TILES

    // epilogue: u = acc + E (exact identity) + hb
    #pragma unroll
    for (int im = 0; im < 2; im++) {
        const int row0e = bm + wm + im * 16 + (lane >> 2);
        #pragma unroll
        for (int in = 0; in < 2; in++) {
            const int col = bn + wn + in * 8 + ((lane & 3) << 1);
            const float h0 = hb[col], h1 = hb[col + 1];
            g_u[(size_t)row0e * DD + col]
                = acc[im][in][0] + E[(size_t)row0e * DD + col] + h0;
            g_u[(size_t)row0e * DD + col + 1]
                = acc[im][in][1] + E[(size_t)row0e * DD + col + 1] + h1;
            g_u[(size_t)(row0e + 8) * DD + col]
                = acc[im][in][2] + E[(size_t)(row0e + 8) * DD + col] + h0;
            g_u[(size_t)(row0e + 8) * DD + col + 1]
                = acc[im][in][3] + E[(size_t)(row0e + 8) * DD + col + 1] + h1;
        }
    }
}

// ---------------------------------------------------------------------------
// Kernel B: scoring, restructured against cross-CTA L1tex front-batch spread:
//  - u_s staged via cp.async (NO front-batched LDGs -> MLP_p1 ~ 0)
//  - vb/pos dots moved to the TAIL (E is L2-resident; ~1us)
// grid (256, 8) x 128 thr, 16 CTAs/SM (single wave).
// ---------------------------------------------------------------------------
__global__ __launch_bounds__(128, 16) void score_kernel(
    const float* __restrict__ E,
    const float* __restrict__ theo,
    const float* __restrict__ cand,
    const float* __restrict__ vb,
    float* __restrict__ out)
{
    const int b    = blockIdx.x;
    const int tc   = blockIdx.y;       // 0..7
    const int tid  = threadIdx.x;
    const int lane = tid & 31;
    const int wid  = tid >> 5;         // 0..3

    __shared__ __align__(16) float u_s[DD];
    __shared__ float red[8];
    __shared__ float s_vb, s_pos;

    // stage u[b] via cp.async: 512 16B chunks, 4 per thread
    {
        const uint32_t su = (uint32_t)__cvta_generic_to_shared(u_s);
        const char* gu = (const char*)(g_u + (size_t)b * DD);
        #pragma unroll
        for (int j = 0; j < 4; j++) {
            const int c = tid + j * 128;
            cp16(su + (uint32_t)(c * 16), gu + c * 16);
        }
        asm volatile("cp.async.commit_group;\n" ::: "memory");
        asm volatile("cp.async.wait_group 0;\n" ::: "memory");
    }
    __syncthreads();

    // mainloop: warp w -> theo rows tc*8 + 2w, +1
    const int t0 = tc * 8 + wid * 2;
    const float4* ra  = reinterpret_cast<const float4*>(&theo[((size_t)b * TT + t0) * DD]);
    const float4* rb  = ra + DD / 4;
    const float4* u4p = reinterpret_cast<const float4*>(u_s);

    float s0 = 0.f, s1 = 0.f;
    #pragma unroll 4
    for (int i = lane; i < DD / 4; i += 32) {
        float4 x = __ldcs(&ra[i]);
        float4 y = __ldcs(&rb[i]);
        float4 u = u4p[i];
        s0 += x.x * u.x + x.y * u.y + x.z * u.z + x.w * u.w;
        s1 += y.x * u.x + y.y * u.y + y.z * u.z + y.w * u.w;
    }
    #pragma unroll
    for (int o = 16; o > 0; o >>= 1) {
        s0 += __shfl_xor_sync(0xFFFFFFFFu, s0, o);
        s1 += __shfl_xor_sync(0xFFFFFFFFu, s1, o);
    }

    // tail: vb dot (all CTAs; E is L2-resident) and pos dot (tc==0 only)
    float pv = 0.f, pp = 0.f;
    #pragma unroll
    for (int h = 0; h < 4; h++) {
        const int i = h * 512 + tid * 4;
        float4 e4 = *reinterpret_cast<const float4*>(&E[(size_t)b * DD + i]);
        float4 v4 = *reinterpret_cast<const float4*>(&vb[i]);
        pv += e4.x * v4.x + e4.y * v4.y + e4.z * v4.z + e4.w * v4.w;
        if (tc == 0) {
            float4 c4 = *reinterpret_cast<const float4*>(&cand[(size_t)b * DD + i]);
            float4 u4 = *reinterpret_cast<const float4*>(&u_s[i]);
            pp += u4.x * c4.x + u4.y * c4.y + u4.z * c4.z + u4.w * c4.w;
        }
    }
    #pragma unroll
    for (int o = 16; o > 0; o >>= 1) {
        pv += __shfl_xor_sync(0xFFFFFFFFu, pv, o);
        pp += __shfl_xor_sync(0xFFFFFFFFu, pp, o);
    }
    if (lane == 0) { red[wid] = pv; red[4 + wid] = pp; }
    __syncthreads();
    if (tid == 0) {
        float v = red[0] + red[1] + red[2] + red[3];
        float p = red[4] + red[5] + red[6] + red[7];
        s_vb  = v;
        s_pos = p + v;
    }
    __syncthreads();
    const float vbb = s_vb;

    if (lane == 0) {
        out[b * (TT + 1) + 1 + t0]     = s0 + vbb;
        out[b * (TT + 1) + 1 + t0 + 1] = s1 + vbb;
    }
    if (tc == 0 && tid == 0) out[b * (TT + 1)] = s_pos;
}

// ---------------------------------------------------------------------------
// launch: 0=experimental [B,D], 1=theoretical [B,T,D], 2=candidate [B,D],
//         3=W [D,D], 4=vb [D], 5=hb [D] ; out fp32 [B, 1+T]
// ---------------------------------------------------------------------------
extern "C" void kernel_launch(void* const* d_in, const int* in_sizes, int n_in,
                              void* d_out, int out_size)
{
    const float* E    = (const float*)d_in[0];
    const float* theo = (const float*)d_in[1];
    const float* cand = (const float*)d_in[2];
    const float* W    = (const float*)d_in[3];
    const float* vb   = (const float*)d_in[4];
    const float* hb   = (const float*)d_in[5];
    float*       out  = (float*)d_out;

    const int SMEM = 12 * 8192;   // 96 KB dynamic
    cudaFuncSetAttribute(gemm_u_kernel,
                         cudaFuncAttributeMaxDynamicSharedMemorySize, SMEM);

    const int npairs = DD * DD / 8 + BB * DD / 8;   // 589824
    convert_kernel<<<npairs / 256, 256>>>(E, W);
    gemm_u_kernel<<<dim3(DD / 64, BB / 64), 256, SMEM>>>(E, hb);
    score_kernel<<<dim3(BB, 8), 128>>>(E, theo, cand, vb, out);
}